// round 4
// baseline (speedup 1.0000x reference)
#include <cuda_runtime.h>
#include <cuda_bf16.h>
#include <math.h>

// Problem constants
#define BATCH   2
#define SEQ     2048
#define DMODEL  2048
#define NHEADS  16
#define DHEAD   128
#define NTOK    (BATCH * SEQ)        // 4096 tokens

// ---------------------------------------------------------------------------
// Scratch buffers (static device globals; no runtime allocation allowed)
// ---------------------------------------------------------------------------
__device__ float g_Q[(size_t)NTOK * DMODEL];
__device__ float g_K[(size_t)NTOK * DMODEL];
__device__ float g_V[(size_t)NTOK * DMODEL];
__device__ float g_C[(size_t)NTOK * DMODEL];

// ---------------------------------------------------------------------------
// SGEMM: Y[M,N] = X[M,K] @ W[N,K]^T   (both operands K-major, fp32)
// Tile 128x128x32, 256 threads, 8x8 per-thread register tile.
// M=4096, N=2048, K=2048 all divide tile sizes -> no bounds checks.
// ---------------------------------------------------------------------------
#define BM 128
#define BN 128
#define BK 32
#define TM 8
#define TN 8
#define PAD_ROW (BM + 4)   // 132 floats, keeps float4 alignment (132 % 4 == 0)

__global__ __launch_bounds__(256, 2)
void sgemm_nt_kernel(const float* __restrict__ X,
                     const float* __restrict__ W,
                     float* __restrict__ Y,
                     int M, int N, int K)
{
    __shared__ float As[BK * PAD_ROW];   // 32 x 132 floats
    __shared__ float Bs[BK * PAD_ROW];

    const int tid = threadIdx.x;
    const int bm  = blockIdx.y * BM;
    const int bn  = blockIdx.x * BN;
    const int tx  = tid & 15;          // 0..15
    const int ty  = tid >> 4;          // 0..15

    float acc[TM][TN];
#pragma unroll
    for (int i = 0; i < TM; ++i)
#pragma unroll
        for (int j = 0; j < TN; ++j)
            acc[i][j] = 0.0f;

    for (int kt = 0; kt < K; kt += BK) {
        // Load A tile (BM x BK) and B tile (BN x BK), transposed into smem.
        // 128 rows x 8 float4 per operand = 1024 float4, 4 per thread.
#pragma unroll
        for (int u = 0; u < 4; ++u) {
            int f   = tid + u * 256;      // 0..1023
            int row = f >> 3;             // 0..127
            int c4  = (f & 7) * 4;        // 0,4,...,28
            float4 a = *(const float4*)&X[(bm + row) * K + kt + c4];
            As[(c4 + 0) * PAD_ROW + row] = a.x;
            As[(c4 + 1) * PAD_ROW + row] = a.y;
            As[(c4 + 2) * PAD_ROW + row] = a.z;
            As[(c4 + 3) * PAD_ROW + row] = a.w;
            float4 b = *(const float4*)&W[(bn + row) * K + kt + c4];
            Bs[(c4 + 0) * PAD_ROW + row] = b.x;
            Bs[(c4 + 1) * PAD_ROW + row] = b.y;
            Bs[(c4 + 2) * PAD_ROW + row] = b.z;
            Bs[(c4 + 3) * PAD_ROW + row] = b.w;
        }
        __syncthreads();

#pragma unroll
        for (int kk = 0; kk < BK; ++kk) {
            float a[TM], b[TN];
            *(float4*)&a[0] = *(float4*)&As[kk * PAD_ROW + ty * TM];
            *(float4*)&a[4] = *(float4*)&As[kk * PAD_ROW + ty * TM + 4];
            *(float4*)&b[0] = *(float4*)&Bs[kk * PAD_ROW + tx * TN];
            *(float4*)&b[4] = *(float4*)&Bs[kk * PAD_ROW + tx * TN + 4];
#pragma unroll
            for (int i = 0; i < TM; ++i)
#pragma unroll
                for (int j = 0; j < TN; ++j)
                    acc[i][j] = fmaf(a[i], b[j], acc[i][j]);
        }
        __syncthreads();
    }

#pragma unroll
    for (int i = 0; i < TM; ++i) {
        int row = bm + ty * TM + i;
        float4 o0 = make_float4(acc[i][0], acc[i][1], acc[i][2], acc[i][3]);
        float4 o1 = make_float4(acc[i][4], acc[i][5], acc[i][6], acc[i][7]);
        *(float4*)&Y[row * N + bn + tx * TN]     = o0;
        *(float4*)&Y[row * N + bn + tx * TN + 4] = o1;
    }
}

// ---------------------------------------------------------------------------
// RoPE: in-place on Q and K, layout (token, h*128 + d).
// out[d]    = x[d]*cos[d]       - x[d+64]*sin[d]
// out[d+64] = x[d+64]*cos[d+64] + x[d]*sin[d+64]
// One thread per (token, head, d<64) pair.  Total 4096*16*64 = 4,194,304.
// ---------------------------------------------------------------------------
__global__ void rope_kernel(float* __restrict__ Q, float* __restrict__ K,
                            const float* __restrict__ cosT,
                            const float* __restrict__ sinT)
{
    int i = blockIdx.x * blockDim.x + threadIdx.x;
    if (i >= NTOK * NHEADS * 64) return;
    int d     = i & 63;
    int h     = (i >> 6) & (NHEADS - 1);
    int token = i >> 10;                // b*SEQ + s
    int s     = token & (SEQ - 1);

    int base = token * DMODEL + h * DHEAD;
    float c1 = cosT[s * DHEAD + d];
    float s1 = sinT[s * DHEAD + d];
    float c2 = cosT[s * DHEAD + d + 64];
    float s2 = sinT[s * DHEAD + d + 64];

    float q1 = Q[base + d], q2 = Q[base + d + 64];
    Q[base + d]      = q1 * c1 - q2 * s1;
    Q[base + d + 64] = q2 * c2 + q1 * s2;

    float k1 = K[base + d], k2 = K[base + d + 64];
    K[base + d]      = k1 * c1 - k2 * s1;
    K[base + d + 64] = k2 * c2 + k1 * s2;
}

// ---------------------------------------------------------------------------
// Causal flash attention, fp32 SIMT.
// Block = (qtile, head, batch): 64 q-rows, iterate 64-col K/V tiles kt<=qt.
// 256 threads = 8 warps; warp w owns q-rows w*8..w*8+7.
// Per lane: score cols {lane, lane+32}; output dims lane*4..lane*4+3.
// ---------------------------------------------------------------------------
#define FA_BR   64
#define FA_BC   64
#define FA_PAD  132   // 128 + 4 floats per smem row
#define FA_PPAD 68    // 64 + 4
#define FA_SMEM ((3 * FA_BR * FA_PAD + FA_BR * FA_PPAD) * 4)   // 118784 bytes

__global__ __launch_bounds__(256, 1)
void flash_attn_kernel(const float* __restrict__ Q,
                       const float* __restrict__ K,
                       const float* __restrict__ V,
                       float* __restrict__ O)
{
    extern __shared__ float sm[];
    float* Qs = sm;                           // 64 x 132
    float* Ks = Qs + FA_BR * FA_PAD;          // 64 x 132
    float* Vs = Ks + FA_BR * FA_PAD;          // 64 x 132
    float* Ps = Vs + FA_BR * FA_PAD;          // 64 x 68

    const int tid  = threadIdx.x;
    const int lane = tid & 31;
    const int warp = tid >> 5;
    const int qt   = blockIdx.x;              // 0..31
    const int h    = blockIdx.y;              // 0..15
    const int b    = blockIdx.z;              // 0..1
    const int q0   = qt * FA_BR;
    const float scale = 0.08838834764831845f; // 1/sqrt(128)

    const float* Qb = Q + (size_t)(b * SEQ) * DMODEL + h * DHEAD;
    const float* Kb = K + (size_t)(b * SEQ) * DMODEL + h * DHEAD;
    const float* Vb = V + (size_t)(b * SEQ) * DMODEL + h * DHEAD;
    float*       Ob = O + (size_t)(b * SEQ) * DMODEL + h * DHEAD;

    // Load + pre-scale Q tile: 64 rows x 32 float4
    for (int f = tid; f < FA_BR * 32; f += 256) {
        int r  = f >> 5;
        int c4 = (f & 31) * 4;
        float4 v = *(const float4*)&Qb[(size_t)(q0 + r) * DMODEL + c4];
        v.x *= scale; v.y *= scale; v.z *= scale; v.w *= scale;
        *(float4*)&Qs[r * FA_PAD + c4] = v;
    }

    const int r_base = warp * 8;
    const int d0     = lane * 4;

    float m_i[8], l_i[8], acc[8][4];
#pragma unroll
    for (int i = 0; i < 8; ++i) {
        m_i[i] = -1e30f;
        l_i[i] = 0.0f;
        acc[i][0] = acc[i][1] = acc[i][2] = acc[i][3] = 0.0f;
    }

    for (int kt = 0; kt <= qt; ++kt) {
        const int k0 = kt * FA_BC;
        __syncthreads();   // previous-iteration Ks/Vs readers done (also orders Qs writes)

        for (int f = tid; f < FA_BC * 32; f += 256) {
            int r  = f >> 5;
            int c4 = (f & 31) * 4;
            *(float4*)&Ks[r * FA_PAD + c4] =
                *(const float4*)&Kb[(size_t)(k0 + r) * DMODEL + c4];
            *(float4*)&Vs[r * FA_PAD + c4] =
                *(const float4*)&Vb[(size_t)(k0 + r) * DMODEL + c4];
        }
        __syncthreads();

        // S = Qs . Ks^T   (lane cols: lane, lane+32)
        float s[8][2];
#pragma unroll
        for (int i = 0; i < 8; ++i) { s[i][0] = 0.0f; s[i][1] = 0.0f; }

#pragma unroll
        for (int k = 0; k < DHEAD; k += 4) {
            float4 kA = *(float4*)&Ks[lane * FA_PAD + k];
            float4 kB = *(float4*)&Ks[(lane + 32) * FA_PAD + k];
#pragma unroll
            for (int i = 0; i < 8; ++i) {
                float4 q = *(float4*)&Qs[(r_base + i) * FA_PAD + k];
                s[i][0] = fmaf(q.x, kA.x, s[i][0]);
                s[i][0] = fmaf(q.y, kA.y, s[i][0]);
                s[i][0] = fmaf(q.z, kA.z, s[i][0]);
                s[i][0] = fmaf(q.w, kA.w, s[i][0]);
                s[i][1] = fmaf(q.x, kB.x, s[i][1]);
                s[i][1] = fmaf(q.y, kB.y, s[i][1]);
                s[i][1] = fmaf(q.z, kB.z, s[i][1]);
                s[i][1] = fmaf(q.w, kB.w, s[i][1]);
            }
        }

        // Causal mask on the diagonal tile
        if (kt == qt) {
#pragma unroll
            for (int i = 0; i < 8; ++i) {
                int rg = q0 + r_base + i;
                if (k0 + lane      > rg) s[i][0] = -1e30f;
                if (k0 + lane + 32 > rg) s[i][1] = -1e30f;
            }
        }

        // Online softmax (per-warp rows; full-warp shfl reductions)
#pragma unroll
        for (int i = 0; i < 8; ++i) {
            float mx = fmaxf(s[i][0], s[i][1]);
#pragma unroll
            for (int off = 16; off > 0; off >>= 1)
                mx = fmaxf(mx, __shfl_xor_sync(0xFFFFFFFFu, mx, off));
            float m_new = fmaxf(m_i[i], mx);
            float p0 = __expf(s[i][0] - m_new);
            float p1 = __expf(s[i][1] - m_new);
            float rs = p0 + p1;
#pragma unroll
            for (int off = 16; off > 0; off >>= 1)
                rs += __shfl_xor_sync(0xFFFFFFFFu, rs, off);
            float alpha = __expf(m_i[i] - m_new);
            l_i[i] = l_i[i] * alpha + rs;
            m_i[i] = m_new;
            acc[i][0] *= alpha; acc[i][1] *= alpha;
            acc[i][2] *= alpha; acc[i][3] *= alpha;
            Ps[(r_base + i) * FA_PPAD + lane]      = p0;
            Ps[(r_base + i) * FA_PPAD + lane + 32] = p1;
        }
        __syncwarp();   // Ps rows are warp-private: warp-level ordering suffices

        // O += P . V   (lane dims d0..d0+3)
#pragma unroll
        for (int c = 0; c < FA_BC; c += 4) {
            float4 v0 = *(float4*)&Vs[(c + 0) * FA_PAD + d0];
            float4 v1 = *(float4*)&Vs[(c + 1) * FA_PAD + d0];
            float4 v2 = *(float4*)&Vs[(c + 2) * FA_PAD + d0];
            float4 v3 = *(float4*)&Vs[(c + 3) * FA_PAD + d0];
#pragma unroll
            for (int i = 0; i < 8; ++i) {
                float4 p = *(float4*)&Ps[(r_base + i) * FA_PPAD + c];
                acc[i][0] = fmaf(p.x, v0.x, acc[i][0]);
                acc[i][0] = fmaf(p.y, v1.x, acc[i][0]);
                acc[i][0] = fmaf(p.z, v2.x, acc[i][0]);
                acc[i][0] = fmaf(p.w, v3.x, acc[i][0]);
                acc[i][1] = fmaf(p.x, v0.y, acc[i][1]);
                acc[i][1] = fmaf(p.y, v1.y, acc[i][1]);
                acc[i][1] = fmaf(p.z, v2.y, acc[i][1]);
                acc[i][1] = fmaf(p.w, v3.y, acc[i][1]);
                acc[i][2] = fmaf(p.x, v0.z, acc[i][2]);
                acc[i][2] = fmaf(p.y, v1.z, acc[i][2]);
                acc[i][2] = fmaf(p.z, v2.z, acc[i][2]);
                acc[i][2] = fmaf(p.w, v3.z, acc[i][2]);
                acc[i][3] = fmaf(p.x, v0.w, acc[i][3]);
                acc[i][3] = fmaf(p.y, v1.w, acc[i][3]);
                acc[i][3] = fmaf(p.z, v2.w, acc[i][3]);
                acc[i][3] = fmaf(p.w, v3.w, acc[i][3]);
            }
        }
        __syncwarp();  // Ps reads done before next iteration's writes
    }

    // Finalize and write context (token-major, head-contiguous)
#pragma unroll
    for (int i = 0; i < 8; ++i) {
        float inv = 1.0f / l_i[i];
        float4 o = make_float4(acc[i][0] * inv, acc[i][1] * inv,
                               acc[i][2] * inv, acc[i][3] * inv);
        *(float4*)&Ob[(size_t)(q0 + r_base + i) * DMODEL + d0] = o;
    }
}

// ---------------------------------------------------------------------------
// kernel_launch
// Inputs (metadata order): x, cos, sin, Wq, Wk, Wv, Wo  (all fp32)
// Output: (B, S, D_MODEL) fp32
// ---------------------------------------------------------------------------
extern "C" void kernel_launch(void* const* d_in, const int* in_sizes, int n_in,
                              void* d_out, int out_size)
{
    const float* x    = (const float*)d_in[0];
    const float* cosT = (const float*)d_in[1];
    const float* sinT = (const float*)d_in[2];
    const float* Wq   = (const float*)d_in[3];
    const float* Wk   = (const float*)d_in[4];
    const float* Wv   = (const float*)d_in[5];
    const float* Wo   = (const float*)d_in[6];
    float* out = (float*)d_out;

    float *qp, *kp, *vp, *cp;
    cudaGetSymbolAddress((void**)&qp, g_Q);
    cudaGetSymbolAddress((void**)&kp, g_K);
    cudaGetSymbolAddress((void**)&vp, g_V);
    cudaGetSymbolAddress((void**)&cp, g_C);

    cudaFuncSetAttribute(flash_attn_kernel,
                         cudaFuncAttributeMaxDynamicSharedMemorySize, FA_SMEM);

    dim3 ggrid(DMODEL / BN, NTOK / BM);   // (16, 32)

    // QKV projections
    sgemm_nt_kernel<<<ggrid, 256>>>(x, Wq, qp, NTOK, DMODEL, DMODEL);
    sgemm_nt_kernel<<<ggrid, 256>>>(x, Wk, kp, NTOK, DMODEL, DMODEL);
    sgemm_nt_kernel<<<ggrid, 256>>>(x, Wv, vp, NTOK, DMODEL, DMODEL);

    // RoPE on Q and K
    int rope_threads = NTOK * NHEADS * 64;
    rope_kernel<<<(rope_threads + 255) / 256, 256>>>(qp, kp, cosT, sinT);

    // Causal flash attention
    dim3 fgrid(SEQ / FA_BR, NHEADS, BATCH);   // (32, 16, 2)
    flash_attn_kernel<<<fgrid, 256, FA_SMEM>>>(qp, kp, vp, cp);

    // Output projection -> d_out
    sgemm_nt_kernel<<<ggrid, 256>>>(cp, Wo, out, NTOK, DMODEL, DMODEL);
}

// round 8
// speedup vs baseline: 1.4537x; 1.4537x over previous
#include <cuda_runtime.h>
#include <cuda_bf16.h>
#include <stdint.h>
#include <math.h>

// Problem constants
#define BATCH   2
#define SEQ     2048
#define DMODEL  2048
#define NHEADS  16
#define DHEAD   128
#define NTOK    (BATCH * SEQ)        // 4096 tokens

// ---------------------------------------------------------------------------
// Scratch buffers (static device globals; no runtime allocation allowed)
// ---------------------------------------------------------------------------
__device__ float g_Q[(size_t)NTOK * DMODEL];
__device__ float g_K[(size_t)NTOK * DMODEL];
__device__ float g_V[(size_t)NTOK * DMODEL];
__device__ float g_C[(size_t)NTOK * DMODEL];

// ===========================================================================
// Helpers
// ===========================================================================
__device__ __forceinline__ uint32_t smem_to_u32(const void* p) {
    uint32_t a;
    asm("{ .reg .u64 t; cvta.to.shared.u64 t, %1; cvt.u32.u64 %0, t; }"
        : "=r"(a) : "l"(p));
    return a;
}

#define LDSM_X4(r0, r1, r2, r3, addr) \
    asm volatile("ldmatrix.sync.aligned.m8n8.x4.shared.b16 {%0,%1,%2,%3}, [%4];" \
                 : "=r"(r0), "=r"(r1), "=r"(r2), "=r"(r3) : "r"(addr))

#define MMA_BF16(d, a, b0, b1) \
    asm volatile("mma.sync.aligned.m16n8k16.row.col.f32.bf16.bf16.f32 " \
                 "{%0,%1,%2,%3}, {%4,%5,%6,%7}, {%8,%9}, {%0,%1,%2,%3};" \
                 : "+f"((d)[0]), "+f"((d)[1]), "+f"((d)[2]), "+f"((d)[3]) \
                 : "r"((a)[0]), "r"((a)[1]), "r"((a)[2]), "r"((a)[3]), \
                   "r"(b0), "r"(b1))

// Split two floats into packed bf16 hi pair (returned) and lo pair (out).
__device__ __forceinline__ uint32_t packsplit2(float a, float b, uint32_t& lo_out) {
    __nv_bfloat16 ha = __float2bfloat16_rn(a);
    __nv_bfloat16 hb = __float2bfloat16_rn(b);
    float la = a - __bfloat162float(ha);
    float lb = b - __bfloat162float(hb);
    __nv_bfloat16 hla = __float2bfloat16_rn(la);
    __nv_bfloat16 hlb = __float2bfloat16_rn(lb);
    lo_out = ((uint32_t)__bfloat16_as_ushort(hlb) << 16) |
             (uint32_t)__bfloat16_as_ushort(hla);
    return ((uint32_t)__bfloat16_as_ushort(hb) << 16) |
           (uint32_t)__bfloat16_as_ushort(ha);
}

// ===========================================================================
// Tensor-core GEMM via mma.sync (bf16 x2 split): Y[M,N] = X[M,K] @ W[N,K]^T
// Block 128x128, BK=32, double-buffered smem (hi/lo planes for A and B).
// 8 warps: warp_m = warp&3 (32 rows), warp_n = warp>>2 (64 cols).
// ===========================================================================
#define MM_BM 128
#define MM_BN 128
#define MM_BK 32
// stage layout (bytes): A_hi[0,8K) A_lo[8K,16K) B_hi[16K,24K) B_lo[24K,32K)
#define MM_AHI 0
#define MM_ALO 8192
#define MM_BHI 16384
#define MM_BLO 24576
#define MM_STAGE 32768
#define MM_SMEM (2 * MM_STAGE)     // 65536 bytes

// swizzled byte offset of 16B chunk `ch` (0..3) in row `row` (64B rows)
__device__ __forceinline__ uint32_t sw_off(int row, int ch) {
    return (uint32_t)(row * 64 + ((ch ^ ((row >> 1) & 3)) << 4));
}

__global__ __launch_bounds__(256, 1)
void gemm_mma_kernel(const float* __restrict__ X,
                     const float* __restrict__ W,
                     float* __restrict__ Y,
                     int M, int N, int K)
{
    extern __shared__ char smem[];
    const uint32_t smem_u32 = smem_to_u32(smem);

    const int tid  = threadIdx.x;
    const int lane = tid & 31;
    const int warp = tid >> 5;
    const int wm   = warp & 3;      // 0..3 -> 32-row slice
    const int wn   = warp >> 2;     // 0..1 -> 64-col slice
    const int bm   = blockIdx.y * MM_BM;
    const int bn   = blockIdx.x * MM_BN;

    // Loader mapping: 256 threads, 128 rows x 2 halves of 16 floats.
    const int lrow  = tid >> 1;         // 0..127
    const int lhalf = tid & 1;          // 0..1 (floats 16*lhalf .. +15)

    const float* Arow = X + (size_t)(bm + lrow) * K + lhalf * 16;
    const float* Brow = W + (size_t)(bn + lrow) * K + lhalf * 16;

    float4 ra[4], rb[4];
    const int nchunk = K / MM_BK;

    // Prefetch chunk 0
#pragma unroll
    for (int j = 0; j < 4; ++j) {
        ra[j] = *(const float4*)&Arow[j * 4];
        rb[j] = *(const float4*)&Brow[j * 4];
    }

    float acc[2][8][4];
#pragma unroll
    for (int mf = 0; mf < 2; ++mf)
#pragma unroll
        for (int nf = 0; nf < 8; ++nf)
#pragma unroll
            for (int q = 0; q < 4; ++q)
                acc[mf][nf][q] = 0.0f;

    for (int c = 0; c < nchunk; ++c) {
        const int s = c & 1;
        char* sbuf = smem + s * MM_STAGE;

        // Store regs (chunk c) -> smem, split hi/lo
#pragma unroll
        for (int j2 = 0; j2 < 2; ++j2) {
            const int ch = lhalf * 2 + j2;
            uint32_t aoff = sw_off(lrow, ch);
            uint4 hi, lo;
            hi.x = packsplit2(ra[2 * j2].x,     ra[2 * j2].y,     lo.x);
            hi.y = packsplit2(ra[2 * j2].z,     ra[2 * j2].w,     lo.y);
            hi.z = packsplit2(ra[2 * j2 + 1].x, ra[2 * j2 + 1].y, lo.z);
            hi.w = packsplit2(ra[2 * j2 + 1].z, ra[2 * j2 + 1].w, lo.w);
            *(uint4*)(sbuf + MM_AHI + aoff) = hi;
            *(uint4*)(sbuf + MM_ALO + aoff) = lo;
            hi.x = packsplit2(rb[2 * j2].x,     rb[2 * j2].y,     lo.x);
            hi.y = packsplit2(rb[2 * j2].z,     rb[2 * j2].w,     lo.y);
            hi.z = packsplit2(rb[2 * j2 + 1].x, rb[2 * j2 + 1].y, lo.z);
            hi.w = packsplit2(rb[2 * j2 + 1].z, rb[2 * j2 + 1].w, lo.w);
            *(uint4*)(sbuf + MM_BHI + aoff) = hi;
            *(uint4*)(sbuf + MM_BLO + aoff) = lo;
        }
        __syncthreads();

        // Prefetch chunk c+1 (gmem latency hidden by compute below)
        if (c + 1 < nchunk) {
            const float* An = Arow + (size_t)(c + 1) * MM_BK;
            const float* Bn = Brow + (size_t)(c + 1) * MM_BK;
#pragma unroll
            for (int j = 0; j < 4; ++j) {
                ra[j] = *(const float4*)&An[j * 4];
                rb[j] = *(const float4*)&Bn[j * 4];
            }
        }

        // Compute on stage s
        const uint32_t sAhi = smem_u32 + s * MM_STAGE + MM_AHI;
        const uint32_t sAlo = smem_u32 + s * MM_STAGE + MM_ALO;
        const uint32_t sBhi = smem_u32 + s * MM_STAGE + MM_BHI;
        const uint32_t sBlo = smem_u32 + s * MM_STAGE + MM_BLO;

#pragma unroll
        for (int ks = 0; ks < 2; ++ks) {
            uint32_t ah[2][4], al[2][4];
#pragma unroll
            for (int mf = 0; mf < 2; ++mf) {
                int row = wm * 32 + mf * 16 + (lane & 15);
                int ch  = ks * 2 + (lane >> 4);
                uint32_t off = sw_off(row, ch);
                LDSM_X4(ah[mf][0], ah[mf][1], ah[mf][2], ah[mf][3], sAhi + off);
                LDSM_X4(al[mf][0], al[mf][1], al[mf][2], al[mf][3], sAlo + off);
            }
            uint32_t bh[4][4], bl[4][4];
#pragma unroll
            for (int nf2 = 0; nf2 < 4; ++nf2) {
                int row = wn * 64 + nf2 * 16 + (lane & 15);
                int ch  = ks * 2 + (lane >> 4);
                uint32_t off = sw_off(row, ch);
                LDSM_X4(bh[nf2][0], bh[nf2][1], bh[nf2][2], bh[nf2][3], sBhi + off);
                LDSM_X4(bl[nf2][0], bl[nf2][1], bl[nf2][2], bl[nf2][3], sBlo + off);
            }
#pragma unroll
            for (int mf = 0; mf < 2; ++mf)
#pragma unroll
                for (int nf2 = 0; nf2 < 4; ++nf2)
#pragma unroll
                    for (int sub = 0; sub < 2; ++sub) {
                        float* d = acc[mf][nf2 * 2 + sub];
                        MMA_BF16(d, ah[mf], bh[nf2][sub], bh[nf2][sub + 2]);
                        MMA_BF16(d, ah[mf], bl[nf2][sub], bl[nf2][sub + 2]);
                        MMA_BF16(d, al[mf], bh[nf2][sub], bh[nf2][sub + 2]);
                    }
        }
        __syncthreads();
    }

    // Epilogue: c-frag m16n8 layout: rows (lane>>2)+{0,8}, cols (lane&3)*2+{0,1}
#pragma unroll
    for (int mf = 0; mf < 2; ++mf) {
        int r0 = bm + wm * 32 + mf * 16 + (lane >> 2);
#pragma unroll
        for (int nf = 0; nf < 8; ++nf) {
            int col = bn + wn * 64 + nf * 8 + (lane & 3) * 2;
            float2 v0 = make_float2(acc[mf][nf][0], acc[mf][nf][1]);
            float2 v1 = make_float2(acc[mf][nf][2], acc[mf][nf][3]);
            *(float2*)&Y[(size_t)r0 * N + col]       = v0;
            *(float2*)&Y[(size_t)(r0 + 8) * N + col] = v1;
        }
    }
}

// ---------------------------------------------------------------------------
// RoPE: in-place on Q and K, layout (token, h*128 + d).
// ---------------------------------------------------------------------------
__global__ void rope_kernel(float* __restrict__ Q, float* __restrict__ K,
                            const float* __restrict__ cosT,
                            const float* __restrict__ sinT)
{
    int i = blockIdx.x * blockDim.x + threadIdx.x;
    if (i >= NTOK * NHEADS * 64) return;
    int d     = i & 63;
    int h     = (i >> 6) & (NHEADS - 1);
    int token = i >> 10;                // b*SEQ + s
    int s     = token & (SEQ - 1);

    int base = token * DMODEL + h * DHEAD;
    float c1 = cosT[s * DHEAD + d];
    float s1 = sinT[s * DHEAD + d];
    float c2 = cosT[s * DHEAD + d + 64];
    float s2 = sinT[s * DHEAD + d + 64];

    float q1 = Q[base + d], q2 = Q[base + d + 64];
    Q[base + d]      = q1 * c1 - q2 * s1;
    Q[base + d + 64] = q2 * c2 + q1 * s2;

    float k1 = K[base + d], k2 = K[base + d + 64];
    K[base + d]      = k1 * c1 - k2 * s1;
    K[base + d + 64] = k2 * c2 + k1 * s2;
}

// ---------------------------------------------------------------------------
// Causal flash attention, fp32 SIMT (unchanged — proven correct, R4).
// ---------------------------------------------------------------------------
#define FA_BR   64
#define FA_BC   64
#define FA_PAD  132
#define FA_PPAD 68
#define FA_SMEM ((3 * FA_BR * FA_PAD + FA_BR * FA_PPAD) * 4)   // 118784 bytes

__global__ __launch_bounds__(256, 1)
void flash_attn_kernel(const float* __restrict__ Q,
                       const float* __restrict__ K,
                       const float* __restrict__ V,
                       float* __restrict__ O)
{
    extern __shared__ float sm[];
    float* Qs = sm;
    float* Ks = Qs + FA_BR * FA_PAD;
    float* Vs = Ks + FA_BR * FA_PAD;
    float* Ps = Vs + FA_BR * FA_PAD;

    const int tid  = threadIdx.x;
    const int lane = tid & 31;
    const int warp = tid >> 5;
    const int qt   = blockIdx.x;
    const int h    = blockIdx.y;
    const int b    = blockIdx.z;
    const int q0   = qt * FA_BR;
    const float scale = 0.08838834764831845f;

    const float* Qb = Q + (size_t)(b * SEQ) * DMODEL + h * DHEAD;
    const float* Kb = K + (size_t)(b * SEQ) * DMODEL + h * DHEAD;
    const float* Vb = V + (size_t)(b * SEQ) * DMODEL + h * DHEAD;
    float*       Ob = O + (size_t)(b * SEQ) * DMODEL + h * DHEAD;

    for (int f = tid; f < FA_BR * 32; f += 256) {
        int r  = f >> 5;
        int c4 = (f & 31) * 4;
        float4 v = *(const float4*)&Qb[(size_t)(q0 + r) * DMODEL + c4];
        v.x *= scale; v.y *= scale; v.z *= scale; v.w *= scale;
        *(float4*)&Qs[r * FA_PAD + c4] = v;
    }

    const int r_base = warp * 8;
    const int d0     = lane * 4;

    float m_i[8], l_i[8], acc[8][4];
#pragma unroll
    for (int i = 0; i < 8; ++i) {
        m_i[i] = -1e30f;
        l_i[i] = 0.0f;
        acc[i][0] = acc[i][1] = acc[i][2] = acc[i][3] = 0.0f;
    }

    for (int kt = 0; kt <= qt; ++kt) {
        const int k0 = kt * FA_BC;
        __syncthreads();

        for (int f = tid; f < FA_BC * 32; f += 256) {
            int r  = f >> 5;
            int c4 = (f & 31) * 4;
            *(float4*)&Ks[r * FA_PAD + c4] =
                *(const float4*)&Kb[(size_t)(k0 + r) * DMODEL + c4];
            *(float4*)&Vs[r * FA_PAD + c4] =
                *(const float4*)&Vb[(size_t)(k0 + r) * DMODEL + c4];
        }
        __syncthreads();

        float s[8][2];
#pragma unroll
        for (int i = 0; i < 8; ++i) { s[i][0] = 0.0f; s[i][1] = 0.0f; }

#pragma unroll
        for (int k = 0; k < DHEAD; k += 4) {
            float4 kA = *(float4*)&Ks[lane * FA_PAD + k];
            float4 kB = *(float4*)&Ks[(lane + 32) * FA_PAD + k];
#pragma unroll
            for (int i = 0; i < 8; ++i) {
                float4 q = *(float4*)&Qs[(r_base + i) * FA_PAD + k];
                s[i][0] = fmaf(q.x, kA.x, s[i][0]);
                s[i][0] = fmaf(q.y, kA.y, s[i][0]);
                s[i][0] = fmaf(q.z, kA.z, s[i][0]);
                s[i][0] = fmaf(q.w, kA.w, s[i][0]);
                s[i][1] = fmaf(q.x, kB.x, s[i][1]);
                s[i][1] = fmaf(q.y, kB.y, s[i][1]);
                s[i][1] = fmaf(q.z, kB.z, s[i][1]);
                s[i][1] = fmaf(q.w, kB.w, s[i][1]);
            }
        }

        if (kt == qt) {
#pragma unroll
            for (int i = 0; i < 8; ++i) {
                int rg = q0 + r_base + i;
                if (k0 + lane      > rg) s[i][0] = -1e30f;
                if (k0 + lane + 32 > rg) s[i][1] = -1e30f;
            }
        }

#pragma unroll
        for (int i = 0; i < 8; ++i) {
            float mx = fmaxf(s[i][0], s[i][1]);
#pragma unroll
            for (int off = 16; off > 0; off >>= 1)
                mx = fmaxf(mx, __shfl_xor_sync(0xFFFFFFFFu, mx, off));
            float m_new = fmaxf(m_i[i], mx);
            float p0 = __expf(s[i][0] - m_new);
            float p1 = __expf(s[i][1] - m_new);
            float rs = p0 + p1;
#pragma unroll
            for (int off = 16; off > 0; off >>= 1)
                rs += __shfl_xor_sync(0xFFFFFFFFu, rs, off);
            float alpha = __expf(m_i[i] - m_new);
            l_i[i] = l_i[i] * alpha + rs;
            m_i[i] = m_new;
            acc[i][0] *= alpha; acc[i][1] *= alpha;
            acc[i][2] *= alpha; acc[i][3] *= alpha;
            Ps[(r_base + i) * FA_PPAD + lane]      = p0;
            Ps[(r_base + i) * FA_PPAD + lane + 32] = p1;
        }
        __syncwarp();

#pragma unroll
        for (int c = 0; c < FA_BC; c += 4) {
            float4 v0 = *(float4*)&Vs[(c + 0) * FA_PAD + d0];
            float4 v1 = *(float4*)&Vs[(c + 1) * FA_PAD + d0];
            float4 v2 = *(float4*)&Vs[(c + 2) * FA_PAD + d0];
            float4 v3 = *(float4*)&Vs[(c + 3) * FA_PAD + d0];
#pragma unroll
            for (int i = 0; i < 8; ++i) {
                float4 p = *(float4*)&Ps[(r_base + i) * FA_PPAD + c];
                acc[i][0] = fmaf(p.x, v0.x, acc[i][0]);
                acc[i][0] = fmaf(p.y, v1.x, acc[i][0]);
                acc[i][0] = fmaf(p.z, v2.x, acc[i][0]);
                acc[i][0] = fmaf(p.w, v3.x, acc[i][0]);
                acc[i][1] = fmaf(p.x, v0.y, acc[i][1]);
                acc[i][1] = fmaf(p.y, v1.y, acc[i][1]);
                acc[i][1] = fmaf(p.z, v2.y, acc[i][1]);
                acc[i][1] = fmaf(p.w, v3.y, acc[i][1]);
                acc[i][2] = fmaf(p.x, v0.z, acc[i][2]);
                acc[i][2] = fmaf(p.y, v1.z, acc[i][2]);
                acc[i][2] = fmaf(p.z, v2.z, acc[i][2]);
                acc[i][2] = fmaf(p.w, v3.z, acc[i][2]);
                acc[i][3] = fmaf(p.x, v0.w, acc[i][3]);
                acc[i][3] = fmaf(p.y, v1.w, acc[i][3]);
                acc[i][3] = fmaf(p.z, v2.w, acc[i][3]);
                acc[i][3] = fmaf(p.w, v3.w, acc[i][3]);
            }
        }
        __syncwarp();
    }

#pragma unroll
    for (int i = 0; i < 8; ++i) {
        float inv = 1.0f / l_i[i];
        float4 o = make_float4(acc[i][0] * inv, acc[i][1] * inv,
                               acc[i][2] * inv, acc[i][3] * inv);
        *(float4*)&Ob[(size_t)(q0 + r_base + i) * DMODEL + d0] = o;
    }
}

// ---------------------------------------------------------------------------
// kernel_launch
// Inputs (metadata order): x, cos, sin, Wq, Wk, Wv, Wo  (all fp32)
// Output: (B, S, D_MODEL) fp32
// ---------------------------------------------------------------------------
extern "C" void kernel_launch(void* const* d_in, const int* in_sizes, int n_in,
                              void* d_out, int out_size)
{
    const float* x    = (const float*)d_in[0];
    const float* cosT = (const float*)d_in[1];
    const float* sinT = (const float*)d_in[2];
    const float* Wq   = (const float*)d_in[3];
    const float* Wk   = (const float*)d_in[4];
    const float* Wv   = (const float*)d_in[5];
    const float* Wo   = (const float*)d_in[6];
    float* out = (float*)d_out;

    float *qp, *kp, *vp, *cp;
    cudaGetSymbolAddress((void**)&qp, g_Q);
    cudaGetSymbolAddress((void**)&kp, g_K);
    cudaGetSymbolAddress((void**)&vp, g_V);
    cudaGetSymbolAddress((void**)&cp, g_C);

    cudaFuncSetAttribute(gemm_mma_kernel,
                         cudaFuncAttributeMaxDynamicSharedMemorySize, MM_SMEM);
    cudaFuncSetAttribute(flash_attn_kernel,
                         cudaFuncAttributeMaxDynamicSharedMemorySize, FA_SMEM);

    dim3 ggrid(DMODEL / MM_BN, NTOK / MM_BM);   // (16, 32)

    // QKV projections (mma.sync bf16 x2-split)
    gemm_mma_kernel<<<ggrid, 256, MM_SMEM>>>(x, Wq, qp, NTOK, DMODEL, DMODEL);
    gemm_mma_kernel<<<ggrid, 256, MM_SMEM>>>(x, Wk, kp, NTOK, DMODEL, DMODEL);
    gemm_mma_kernel<<<ggrid, 256, MM_SMEM>>>(x, Wv, vp, NTOK, DMODEL, DMODEL);

    // RoPE on Q and K
    int rope_threads = NTOK * NHEADS * 64;
    rope_kernel<<<(rope_threads + 255) / 256, 256>>>(qp, kp, cosT, sinT);

    // Causal flash attention
    dim3 fgrid(SEQ / FA_BR, NHEADS, BATCH);   // (32, 16, 2)
    flash_attn_kernel<<<fgrid, 256, FA_SMEM>>>(qp, kp, vp, cp);

    // Output projection -> d_out
    gemm_mma_kernel<<<ggrid, 256, MM_SMEM>>>(cp, Wo, out, NTOK, DMODEL, DMODEL);
}